// round 14
// baseline (speedup 1.0000x reference)
#include <cuda_runtime.h>
#include <cuda_bf16.h>

#define NN 50000
#define NE 1600000
#define NG 512
#define NEG_SLOPE 0.2f
#define SCAN_BLOCKS 196   // 196*256 = 50176 >= NN
#define SCAN_THREADS (SCAN_BLOCKS * 256)
#define GEMM1_BLOCKS 12500      // NN*64 / 256
#define COUNT_BLOCKS 3125       // NE / (256*2)

// ---------------- scratch (device globals; no dynamic alloc allowed) ----------
__device__ int g_deg[SCAN_THREADS];   // zeroed by scanfill each call (static init 0)
__device__ int g_agg[SCAN_BLOCKS];
__device__ int g_ctr1;
__device__ int g_ctr2;
__device__ int g_off[NN + 1];
__device__ int g_cur[NN];
__device__ int g_csrc[NE];

__device__ float g_xl1[NN * 64];
__device__ float g_xr1[NN * 64];
__device__ float g_xl2[NN * 64];
__device__ float g_xr2[NN * 64];
__device__ float g_pool[NG * 64];
__device__ float g_cnt[NG];
__device__ int g_ei64;   // 1 if edge_index is int64
__device__ int g_b64;    // 1 if batch is int64

// ---------------- helpers -----------------------------------------------------
__device__ __forceinline__ float lrelu(float v) {
    return fmaxf(v, NEG_SLOPE * v);
}
__device__ __forceinline__ int ldidx(const void* p, long long i, int is64) {
    return is64 ? (int)((const long long*)p)[i] : ((const int*)p)[i];
}
__device__ __forceinline__ void redAdd4(float* p, float a, float b, float c, float d) {
    asm volatile("red.global.add.v4.f32 [%0], {%1, %2, %3, %4};"
                 :: "l"(p), "f"(a), "f"(b), "f"(c), "f"(d) : "memory");
}
#define FMA2(d, a, b) asm("fma.rn.f32x2 %0, %1, %2, %0;" : "+l"(d) : "l"(a), "l"(b))
#define DUP2(d, f) asm("mov.b64 %0, {%1, %1};" : "=l"(d) : "r"(__float_as_uint(f)))

// ---- k_pre: zero scratch + dtype detect + layer-1 transform + degree count ----
__global__ void k_pre(const float* __restrict__ x,
                      const float* __restrict__ Wl,
                      const float* __restrict__ Wr,
                      const void* __restrict__ ei,
                      const int* __restrict__ batch) {
    int tid = threadIdx.x;
    if (blockIdx.x >= GEMM1_BLOCKS) {
        __shared__ int sh_is64;
        if (tid < 32) {
            const int* e32 = (const int*)ei;
            int v = e32[2 * tid + 1] | e32[2 * (tid + 32) + 1];
            int any = __any_sync(0xffffffffu, v != 0);
            if (tid == 0) sh_is64 = any ? 0 : 1;
        }
        __syncthreads();
        int is64 = sh_is64;
        long long j = (long long)(blockIdx.x - GEMM1_BLOCKS) * 256 + tid;
        int d0, d1;
        if (is64) {
            longlong2 dp = ((const longlong2*)((const long long*)ei + NE))[j];
            d0 = (int)dp.x; d1 = (int)dp.y;
        } else {
            int2 dp = ((const int2*)((const int*)ei + NE))[j];
            d0 = dp.x; d1 = dp.y;
        }
        atomicAdd(&g_deg[d0], 1);
        atomicAdd(&g_deg[d1], 1);
        return;
    }

    int idx = blockIdx.x * 256 + tid;
    if (idx < NG * 64) g_pool[idx] = 0.f;
    if (idx < NG) g_cnt[idx] = 0.f;
    if (idx == 0) { g_ctr1 = 0; g_ctr2 = 0; }

    if (blockIdx.x == 0) {
        if (tid < 32) {
            const int* e32 = (const int*)ei;
            int v = e32[2 * tid + 1] | e32[2 * (tid + 32) + 1];
            int any = __any_sync(0xffffffffu, v != 0);
            if (tid == 0) g_ei64 = any ? 0 : 1;
        } else if (tid < 64) {
            int j = tid - 32;
            int v = batch[NN - 1 - 2 * j] | batch[NN - 1 - 2 * (j + 32)];
            int any = __any_sync(0xffffffffu, v != 0);
            if (tid == 32) g_b64 = any ? 0 : 1;
        }
    }

    int n = idx >> 6, c = idx & 63;
    float x0 = x[n * 5 + 0], x1 = x[n * 5 + 1], x2 = x[n * 5 + 2];
    float x3 = x[n * 5 + 3], x4 = x[n * 5 + 4];
    g_xl1[idx] = x0 * Wl[c] + x1 * Wl[64 + c] + x2 * Wl[128 + c] +
                 x3 * Wl[192 + c] + x4 * Wl[256 + c];
    g_xr1[idx] = x0 * Wr[c] + x1 * Wr[64 + c] + x2 * Wr[128 + c] +
                 x3 * Wr[192 + c] + x4 * Wr[256 + c];
}

// ---- fused CSR: block scans + grid-sync + offsets + grid-sync + 4-edge fill ----
__global__ __launch_bounds__(256) void k_scanfill(const void* __restrict__ ei) {
    __shared__ int sh[256];
    __shared__ int shw[8];
    __shared__ int sh_base;
    int tid = threadIdx.x, b = blockIdx.x;
    int i = b * 256 + tid;
    int v = g_deg[i];
    g_deg[i] = 0;               // reset for next call's counting (k_pre)

    sh[tid] = v;
    __syncthreads();
#pragma unroll
    for (int d = 1; d < 256; d <<= 1) {
        int a = sh[tid];
        int add = (tid >= d) ? sh[tid - d] : 0;
        __syncthreads();
        sh[tid] = a + add;
        __syncthreads();
    }
    int incl = sh[tid];
    if (tid == 255) g_agg[b] = incl;
    __syncthreads();

    if (tid == 0) {
        __threadfence();
        atomicAdd(&g_ctr1, 1);
        while (atomicAdd(&g_ctr1, 0) < SCAN_BLOCKS) __nanosleep(64);
        __threadfence();
    }
    __syncthreads();

    int a = (tid < b) ? g_agg[tid] : 0;
#pragma unroll
    for (int d = 16; d >= 1; d >>= 1) a += __shfl_xor_sync(0xffffffffu, a, d);
    if ((tid & 31) == 0) shw[tid >> 5] = a;
    __syncthreads();
    if (tid == 0) {
        int s = 0;
#pragma unroll
        for (int w = 0; w < 8; w++) s += shw[w];
        sh_base = s;
    }
    __syncthreads();

    int off = sh_base + incl - v;
    if (i < NN) { g_off[i] = off; g_cur[i] = off; }
    if (i == 0) g_off[NN] = NE;

    __syncthreads();
    if (tid == 0) {
        __threadfence();
        atomicAdd(&g_ctr2, 1);
        while (atomicAdd(&g_ctr2, 0) < SCAN_BLOCKS) __nanosleep(64);
        __threadfence();
    }
    __syncthreads();

    // 4 edges per thread-iteration: 4 independent atomic->store chains
    int is64 = g_ei64;
    for (long long base = (long long)i * 4; base < NE;
         base += (long long)SCAN_THREADS * 4) {
        int s0, s1, s2, s3, d0, d1, d2, d3;
        if (is64) {
            const long long* e64 = (const long long*)ei;
            longlong2 sa = *(const longlong2*)(e64 + base);
            longlong2 sb = *(const longlong2*)(e64 + base + 2);
            longlong2 da = *(const longlong2*)(e64 + NE + base);
            longlong2 db = *(const longlong2*)(e64 + NE + base + 2);
            s0 = (int)sa.x; s1 = (int)sa.y; s2 = (int)sb.x; s3 = (int)sb.y;
            d0 = (int)da.x; d1 = (int)da.y; d2 = (int)db.x; d3 = (int)db.y;
        } else {
            const int* e32 = (const int*)ei;
            int4 sp = *(const int4*)(e32 + base);
            int4 dp = *(const int4*)(e32 + NE + base);
            s0 = sp.x; s1 = sp.y; s2 = sp.z; s3 = sp.w;
            d0 = dp.x; d1 = dp.y; d2 = dp.z; d3 = dp.w;
        }
        int a0 = atomicAdd(&g_cur[d0], 1);
        int a1 = atomicAdd(&g_cur[d1], 1);
        int a2 = atomicAdd(&g_cur[d2], 1);
        int a3 = atomicAdd(&g_cur[d3], 1);
        g_csrc[a0] = s0;
        g_csrc[a1] = s1;
        g_csrc[a2] = s2;
        g_csrc[a3] = s3;
    }
}

// ---- agg1 FUSED with gemm2: warp per dst (R12 2-edge loop), then per-warp ------
// epilogue computes xl2/xr2 = h1 @ [Wl2|Wr2] from shared. Grid is exactly full
// (6250 blocks x 8 warps = NN), so no early-return warps: syncthreads is safe.
__global__ __launch_bounds__(256) void k_agg1(const float* __restrict__ att,
                                              const float* __restrict__ b1,
                                              const float* __restrict__ Wl2,
                                              const float* __restrict__ Wr2) {
    __shared__ float sW[64][128];   // 32 KB: [k][ Wl cols | Wr cols ]
    __shared__ float sH[8][64];     // 2 KB: per-warp h1 row
    int tid = threadIdx.x;
    for (int i = tid; i < 4096; i += 256) {
        int k = i >> 6, c = i & 63;
        sW[k][c] = Wl2[i];
        sW[k][64 + c] = Wr2[i];
    }
    __syncthreads();

    int wid = tid >> 5;
    int lane = tid & 31;
    int g = lane >> 3, s = lane & 7;
    int n = blockIdx.x * 8 + wid;          // always < NN

    const float4* xr4 = (const float4*)(g_xr1 + n * 64 + s * 8);
    float4 xrA = xr4[0], xrB = xr4[1];
    float4 atA = ((const float4*)(att + s * 8))[0];
    float4 atB = ((const float4*)(att + s * 8))[1];

    float den = 0.f;
    float acc[8] = {0.f, 0.f, 0.f, 0.f, 0.f, 0.f, 0.f, 0.f};

    int k0 = g_off[n];
    int cnt = g_off[n + 1] - k0 + 1;       // edges + self loop
    const int* csrc = g_csrc + k0 - 1;     // csrc[i] valid for 1 <= i < cnt
    int iters = (cnt + 7) >> 3;
    for (int it = 0; it < iters; it++) {
        int i0 = it * 8 + g * 2, i1 = i0 + 1;
        bool v0 = i0 < cnt, v1 = i1 < cnt;
        int s0 = (v0 && i0 > 0) ? csrc[i0] : n;
        int s1 = v1 ? csrc[i1] : n;
        const float4* a40 = (const float4*)(g_xl1 + s0 * 64 + s * 8);
        const float4* a41 = (const float4*)(g_xl1 + s1 * 64 + s * 8);
        float4 a0A = a40[0], a0B = a40[1];
        float4 a1A = a41[0], a1B = a41[1];
        float t0 = atA.x * lrelu(a0A.x + xrA.x) + atA.y * lrelu(a0A.y + xrA.y) +
                   atA.z * lrelu(a0A.z + xrA.z) + atA.w * lrelu(a0A.w + xrA.w) +
                   atB.x * lrelu(a0B.x + xrB.x) + atB.y * lrelu(a0B.y + xrB.y) +
                   atB.z * lrelu(a0B.z + xrB.z) + atB.w * lrelu(a0B.w + xrB.w);
        float t1 = atA.x * lrelu(a1A.x + xrA.x) + atA.y * lrelu(a1A.y + xrA.y) +
                   atA.z * lrelu(a1A.z + xrA.z) + atA.w * lrelu(a1A.w + xrA.w) +
                   atB.x * lrelu(a1B.x + xrB.x) + atB.y * lrelu(a1B.y + xrB.y) +
                   atB.z * lrelu(a1B.z + xrB.z) + atB.w * lrelu(a1B.w + xrB.w);
        t0 += __shfl_xor_sync(0xffffffffu, t0, 1);   // head reduce
        t1 += __shfl_xor_sync(0xffffffffu, t1, 1);
        float p0 = v0 ? __expf(t0) : 0.f;
        float p1 = v1 ? __expf(t1) : 0.f;
        den += p0 + p1;
        acc[0] += p0 * a0A.x + p1 * a1A.x;
        acc[1] += p0 * a0A.y + p1 * a1A.y;
        acc[2] += p0 * a0A.z + p1 * a1A.z;
        acc[3] += p0 * a0A.w + p1 * a1A.w;
        acc[4] += p0 * a0B.x + p1 * a1B.x;
        acc[5] += p0 * a0B.y + p1 * a1B.y;
        acc[6] += p0 * a0B.z + p1 * a1B.z;
        acc[7] += p0 * a0B.w + p1 * a1B.w;
    }
#pragma unroll
    for (int d = 8; d <= 16; d <<= 1) {
        den += __shfl_xor_sync(0xffffffffu, den, d);
#pragma unroll
        for (int j = 0; j < 8; j++) acc[j] += __shfl_xor_sync(0xffffffffu, acc[j], d);
    }
    if (g == 0) {
        float inv = 1.0f / (den + 1e-16f);
        const float4* b4 = (const float4*)(b1 + s * 8);
        float4 bA = b4[0], bB = b4[1];
        float* oh = &sH[wid][s * 8];
        oh[0] = fmaxf(acc[0] * inv + bA.x, 0.f);
        oh[1] = fmaxf(acc[1] * inv + bA.y, 0.f);
        oh[2] = fmaxf(acc[2] * inv + bA.z, 0.f);
        oh[3] = fmaxf(acc[3] * inv + bA.w, 0.f);
        oh[4] = fmaxf(acc[4] * inv + bB.x, 0.f);
        oh[5] = fmaxf(acc[5] * inv + bB.y, 0.f);
        oh[6] = fmaxf(acc[6] * inv + bB.z, 0.f);
        oh[7] = fmaxf(acc[7] * inv + bB.w, 0.f);
    }
    __syncwarp();

    // ---- fused gemm2 epilogue: this warp's node row x [Wl2|Wr2] ----
    unsigned long long accl = 0ull, accr = 0ull;
#pragma unroll 4
    for (int k = 0; k < 64; k++) {
        float xv = sH[wid][k];          // broadcast
        unsigned long long xx;
        DUP2(xx, xv);
        FMA2(accl, xx, *(const unsigned long long*)&sW[k][lane * 2]);
        FMA2(accr, xx, *(const unsigned long long*)&sW[k][64 + lane * 2]);
    }
    *(unsigned long long*)(g_xl2 + n * 64 + lane * 2) = accl;
    *(unsigned long long*)(g_xr2 + n * 64 + lane * 2) = accr;
}

// layer-2 agg: 1 head x 64 dims; 8-lane group reduce; fused mean-pool + count.
// Exact R12 (2-edge) configuration.
__global__ __launch_bounds__(256) void k_agg2(const float* __restrict__ att,
                                              const float* __restrict__ b2,
                                              const void* __restrict__ batch) {
    int warp = (blockIdx.x * 256 + threadIdx.x) >> 5;
    if (warp >= NN) return;
    int lane = threadIdx.x & 31;
    int g = lane >> 3, s = lane & 7;
    int n = warp;

    const float4* xr4 = (const float4*)(g_xr2 + n * 64 + s * 8);
    float4 xrA = xr4[0], xrB = xr4[1];
    float4 atA = ((const float4*)(att + s * 8))[0];
    float4 atB = ((const float4*)(att + s * 8))[1];

    float den = 0.f;
    float acc[8] = {0.f, 0.f, 0.f, 0.f, 0.f, 0.f, 0.f, 0.f};

    int k0 = g_off[n];
    int cnt = g_off[n + 1] - k0 + 1;
    const int* csrc = g_csrc + k0 - 1;
    int iters = (cnt + 7) >> 3;
    for (int it = 0; it < iters; it++) {
        int i0 = it * 8 + g * 2, i1 = i0 + 1;
        bool v0 = i0 < cnt, v1 = i1 < cnt;
        int s0 = (v0 && i0 > 0) ? csrc[i0] : n;
        int s1 = v1 ? csrc[i1] : n;
        const float4* a40 = (const float4*)(g_xl2 + s0 * 64 + s * 8);
        const float4* a41 = (const float4*)(g_xl2 + s1 * 64 + s * 8);
        float4 a0A = a40[0], a0B = a40[1];
        float4 a1A = a41[0], a1B = a41[1];
        float t0 = atA.x * lrelu(a0A.x + xrA.x) + atA.y * lrelu(a0A.y + xrA.y) +
                   atA.z * lrelu(a0A.z + xrA.z) + atA.w * lrelu(a0A.w + xrA.w) +
                   atB.x * lrelu(a0B.x + xrB.x) + atB.y * lrelu(a0B.y + xrB.y) +
                   atB.z * lrelu(a0B.z + xrB.z) + atB.w * lrelu(a0B.w + xrB.w);
        float t1 = atA.x * lrelu(a1A.x + xrA.x) + atA.y * lrelu(a1A.y + xrA.y) +
                   atA.z * lrelu(a1A.z + xrA.z) + atA.w * lrelu(a1A.w + xrA.w) +
                   atB.x * lrelu(a1B.x + xrB.x) + atB.y * lrelu(a1B.y + xrB.y) +
                   atB.z * lrelu(a1B.z + xrB.z) + atB.w * lrelu(a1B.w + xrB.w);
        t0 += __shfl_xor_sync(0xffffffffu, t0, 1);
        t1 += __shfl_xor_sync(0xffffffffu, t1, 1);
        t0 += __shfl_xor_sync(0xffffffffu, t0, 2);
        t1 += __shfl_xor_sync(0xffffffffu, t1, 2);
        t0 += __shfl_xor_sync(0xffffffffu, t0, 4);
        t1 += __shfl_xor_sync(0xffffffffu, t1, 4);
        float p0 = v0 ? __expf(t0) : 0.f;
        float p1 = v1 ? __expf(t1) : 0.f;
        den += p0 + p1;
        acc[0] += p0 * a0A.x + p1 * a1A.x;
        acc[1] += p0 * a0A.y + p1 * a1A.y;
        acc[2] += p0 * a0A.z + p1 * a1A.z;
        acc[3] += p0 * a0A.w + p1 * a1A.w;
        acc[4] += p0 * a0B.x + p1 * a1B.x;
        acc[5] += p0 * a0B.y + p1 * a1B.y;
        acc[6] += p0 * a0B.z + p1 * a1B.z;
        acc[7] += p0 * a0B.w + p1 * a1B.w;
    }
#pragma unroll
    for (int d = 8; d <= 16; d <<= 1) {
        den += __shfl_xor_sync(0xffffffffu, den, d);
#pragma unroll
        for (int j = 0; j < 8; j++) acc[j] += __shfl_xor_sync(0xffffffffu, acc[j], d);
    }
    if (g == 0) {
        float inv = 1.0f / (den + 1e-16f);
        const float4* b4 = (const float4*)(b2 + s * 8);
        float4 bA = b4[0], bB = b4[1];
        float v0f = fmaxf(acc[0] * inv + bA.x, 0.f);
        float v1f = fmaxf(acc[1] * inv + bA.y, 0.f);
        float v2f = fmaxf(acc[2] * inv + bA.z, 0.f);
        float v3f = fmaxf(acc[3] * inv + bA.w, 0.f);
        float v4f = fmaxf(acc[4] * inv + bB.x, 0.f);
        float v5f = fmaxf(acc[5] * inv + bB.y, 0.f);
        float v6f = fmaxf(acc[6] * inv + bB.z, 0.f);
        float v7f = fmaxf(acc[7] * inv + bB.w, 0.f);
        int gid = ldidx(batch, n, g_b64);
        float* dst = g_pool + gid * 64 + s * 8;
        redAdd4(dst + 0, v0f, v1f, v2f, v3f);
        redAdd4(dst + 4, v4f, v5f, v6f, v7f);
        if (s == 0) atomicAdd(&g_cnt[gid], 1.0f);
    }
}

// predictor: out[g] = (pool[g]/max(cnt,1)) . Wp + bp
__global__ void k_pred(const float* __restrict__ Wp, const float* __restrict__ bp,
                       float* __restrict__ out) {
    int g = blockIdx.x * blockDim.x + threadIdx.x;
    if (g >= NG) return;
    float s = 0.f;
#pragma unroll
    for (int c = 0; c < 64; c++) s += g_pool[g * 64 + c] * Wp[c];
    out[g] = s / fmaxf(g_cnt[g], 1.0f) + bp[0];
}

// ---------------- launch --------------------------------------------------------
extern "C" void kernel_launch(void* const* d_in, const int* in_sizes, int n_in,
                              void* d_out, int out_size) {
    const float* x    = (const float*)d_in[0];
    const void*  ei   = d_in[1];
    const void*  batch= d_in[2];
    const float* W1l  = (const float*)d_in[3];
    const float* W1r  = (const float*)d_in[4];
    const float* att1 = (const float*)d_in[5];
    const float* b1   = (const float*)d_in[6];
    const float* W2l  = (const float*)d_in[7];
    const float* W2r  = (const float*)d_in[8];
    const float* att2 = (const float*)d_in[9];
    const float* b2   = (const float*)d_in[10];
    const float* Wp   = (const float*)d_in[11];
    const float* bp   = (const float*)d_in[12];
    float* out = (float*)d_out;

    const int T = 256;
    k_pre<<<GEMM1_BLOCKS + COUNT_BLOCKS, T>>>(x, W1l, W1r, ei, (const int*)batch);
    k_scanfill<<<SCAN_BLOCKS, T>>>(ei);
    k_agg1<<<NN / 8, T>>>(att1, b1, W2l, W2r);          // fused agg1 + gemm2
    k_agg2<<<(NN + 7) / 8, T>>>(att2, b2, batch);       // launch #4 -> profiled
    k_pred<<<(NG + T - 1) / T, T>>>(Wp, bp, out);
}

// round 15
// speedup vs baseline: 1.0501x; 1.0501x over previous
#include <cuda_runtime.h>
#include <cuda_bf16.h>

#define NN 50000
#define NE 1600000
#define NG 512
#define NEG_SLOPE 0.2f
#define GEMM1_BLOCKS 12500      // NN*64 / 256
#define FILL_BLOCKS 3125        // NE / (256*2)
#define CAP 128                 // per-node bucket capacity (max degree ~58)
#define G2M 64                  // nodes per gemm2 block

// ---------------- scratch (device globals; no dynamic alloc allowed) ----------
__device__ int g_deg[NN];          // zeroed by agg2 each call (static init 0)
__device__ int g_csrc[NN * CAP];   // bucketed CSR (25.6 MB)

__device__ float g_xl1[NN * 64];
__device__ float g_xr1[NN * 64];
__device__ float g_h1[NN * 64];
__device__ float g_xl2[NN * 64];
__device__ float g_xr2[NN * 64];
__device__ float g_pool[NG * 64];
__device__ float g_cnt[NG];
__device__ int g_b64;   // 1 if batch is int64

// ---------------- helpers -----------------------------------------------------
__device__ __forceinline__ float lrelu(float v) {
    return fmaxf(v, NEG_SLOPE * v);
}
__device__ __forceinline__ int ldidx(const void* p, long long i, int is64) {
    return is64 ? (int)((const long long*)p)[i] : ((const int*)p)[i];
}
__device__ __forceinline__ void redAdd4(float* p, float a, float b, float c, float d) {
    asm volatile("red.global.add.v4.f32 [%0], {%1, %2, %3, %4};"
                 :: "l"(p), "f"(a), "f"(b), "f"(c), "f"(d) : "memory");
}
#define FMA2(d, a, b) asm("fma.rn.f32x2 %0, %1, %2, %0;" : "+l"(d) : "l"(a), "l"(b))
#define DUP2(d, f) asm("mov.b64 %0, {%1, %1};" : "=l"(d) : "r"(__float_as_uint(f)))

// ---- k_pre: zero pool + dtype detect + layer-1 transform + bucket CSR fill ----
// Blocks [0, GEMM1_BLOCKS): gemm1 + zeroing + batch dtype flag.
// Blocks [GEMM1_BLOCKS, +FILL_BLOCKS): direct bucketed CSR fill (2 edges/thread),
// runs concurrently with gemm1. g_deg is zero at entry (agg2 reset / static init).
__global__ void k_pre(const float* __restrict__ x,
                      const float* __restrict__ Wl,
                      const float* __restrict__ Wr,
                      const void* __restrict__ ei,
                      const int* __restrict__ batch) {
    int tid = threadIdx.x;
    if (blockIdx.x >= GEMM1_BLOCKS) {
        // ---- fill block ----
        __shared__ int sh_is64;
        if (tid < 32) {
            const int* e32 = (const int*)ei;
            int v = e32[2 * tid + 1] | e32[2 * (tid + 32) + 1];
            int any = __any_sync(0xffffffffu, v != 0);
            if (tid == 0) sh_is64 = any ? 0 : 1;
        }
        __syncthreads();
        int is64 = sh_is64;
        long long j = (long long)(blockIdx.x - GEMM1_BLOCKS) * 256 + tid;
        int s0, s1, d0, d1;
        if (is64) {
            const long long* e64 = (const long long*)ei;
            longlong2 sp = ((const longlong2*)e64)[j];
            longlong2 dp = ((const longlong2*)(e64 + NE))[j];
            s0 = (int)sp.x; s1 = (int)sp.y; d0 = (int)dp.x; d1 = (int)dp.y;
        } else {
            const int* e32 = (const int*)ei;
            int2 sp = ((const int2*)e32)[j];
            int2 dp = ((const int2*)(e32 + NE))[j];
            s0 = sp.x; s1 = sp.y; d0 = dp.x; d1 = dp.y;
        }
        int a0 = atomicAdd(&g_deg[d0], 1);
        int a1 = atomicAdd(&g_deg[d1], 1);
        if (a0 < CAP) g_csrc[d0 * CAP + a0] = s0;
        if (a1 < CAP) g_csrc[d1 * CAP + a1] = s1;
        return;
    }

    int idx = blockIdx.x * 256 + tid;
    if (idx < NG * 64) g_pool[idx] = 0.f;
    if (idx < NG) g_cnt[idx] = 0.f;

    if (blockIdx.x == 0 && tid < 32) {
        int v = batch[NN - 1 - 2 * tid] | batch[NN - 1 - 2 * (tid + 32)];
        int any = __any_sync(0xffffffffu, v != 0);
        if (tid == 0) g_b64 = any ? 0 : 1;
    }

    int n = idx >> 6, c = idx & 63;
    float x0 = x[n * 5 + 0], x1 = x[n * 5 + 1], x2 = x[n * 5 + 2];
    float x3 = x[n * 5 + 3], x4 = x[n * 5 + 4];
    g_xl1[idx] = x0 * Wl[c] + x1 * Wl[64 + c] + x2 * Wl[128 + c] +
                 x3 * Wl[192 + c] + x4 * Wl[256 + c];
    g_xr1[idx] = x0 * Wr[c] + x1 * Wr[64 + c] + x2 * Wr[128 + c] +
                 x3 * Wr[192 + c] + x4 * Wr[256 + c];
}

// ------- layer-2 transform: tiled GEMM, conflict-free smem, fp32x2 (R12) --------
__global__ __launch_bounds__(256) void k_gemm2(const float* __restrict__ Wl,
                                               const float* __restrict__ Wr) {
    __shared__ float sX[64][G2M];    // 16 KB, [k][node]
    __shared__ float sW[64][128];    // 32 KB, [k][col]
    int tid = threadIdx.x;
    int nbase = blockIdx.x * G2M;

    for (int i = tid; i < 4096; i += 256) {
        int k = i >> 6, c = i & 63;
        sW[k][c] = Wl[i];
        sW[k][64 + c] = Wr[i];
    }
    for (int i = tid; i < G2M * 16; i += 256) {
        int node = i & (G2M - 1), f4 = i >> 6;
        int n = nbase + node;
        float4 v = make_float4(0.f, 0.f, 0.f, 0.f);
        if (n < NN) v = ((const float4*)(g_h1 + n * 64))[f4];
        sX[f4 * 4 + 0][node] = v.x;
        sX[f4 * 4 + 1][node] = v.y;
        sX[f4 * 4 + 2][node] = v.z;
        sX[f4 * 4 + 3][node] = v.w;
    }
    __syncthreads();

    int tr = tid >> 5;
    int tc = tid & 31;
    int nrow = tr * 8;
    unsigned long long accl[8] = {0,0,0,0,0,0,0,0};
    unsigned long long accr[8] = {0,0,0,0,0,0,0,0};

#pragma unroll 2
    for (int k = 0; k < 64; k++) {
        float4 xa = *(const float4*)&sX[k][nrow];
        float4 xb = *(const float4*)&sX[k][nrow + 4];
        unsigned long long wl = *(const unsigned long long*)&sW[k][tc * 2];
        unsigned long long wr = *(const unsigned long long*)&sW[k][64 + tc * 2];
        unsigned long long xx;
        DUP2(xx, xa.x); FMA2(accl[0], xx, wl); FMA2(accr[0], xx, wr);
        DUP2(xx, xa.y); FMA2(accl[1], xx, wl); FMA2(accr[1], xx, wr);
        DUP2(xx, xa.z); FMA2(accl[2], xx, wl); FMA2(accr[2], xx, wr);
        DUP2(xx, xa.w); FMA2(accl[3], xx, wl); FMA2(accr[3], xx, wr);
        DUP2(xx, xb.x); FMA2(accl[4], xx, wl); FMA2(accr[4], xx, wr);
        DUP2(xx, xb.y); FMA2(accl[5], xx, wl); FMA2(accr[5], xx, wr);
        DUP2(xx, xb.z); FMA2(accl[6], xx, wl); FMA2(accr[6], xx, wr);
        DUP2(xx, xb.w); FMA2(accl[7], xx, wl); FMA2(accr[7], xx, wr);
    }

#pragma unroll
    for (int j = 0; j < 8; j++) {
        int n = nbase + nrow + j;
        if (n < NN) {
            *(unsigned long long*)(g_xl2 + n * 64 + tc * 2) = accl[j];
            *(unsigned long long*)(g_xr2 + n * 64 + tc * 2) = accr[j];
        }
    }
}

// ------- aggregation: warp per dst, 4 groups x 2 edges, direct exp (R12) --------
// Bucketed CSR: cnt = deg[n]+1 (self loop), rows at g_csrc[n*CAP ...].

// layer-1: 4 heads x 16 dims. sublane s owns dims [8s,8s+8) (head = s>>1).
__global__ __launch_bounds__(256) void k_agg1(const float* __restrict__ att,
                                              const float* __restrict__ b1) {
    int warp = (blockIdx.x * 256 + threadIdx.x) >> 5;
    if (warp >= NN) return;
    int lane = threadIdx.x & 31;
    int g = lane >> 3, s = lane & 7;
    int n = warp;

    const float4* xr4 = (const float4*)(g_xr1 + n * 64 + s * 8);
    float4 xrA = xr4[0], xrB = xr4[1];
    float4 atA = ((const float4*)(att + s * 8))[0];
    float4 atB = ((const float4*)(att + s * 8))[1];

    float den = 0.f;
    float acc[8] = {0.f, 0.f, 0.f, 0.f, 0.f, 0.f, 0.f, 0.f};

    int cntE = g_deg[n]; if (cntE > CAP) cntE = CAP;
    int cnt = cntE + 1;                    // edges + self loop
    const int* csrc = g_csrc + n * CAP - 1;  // csrc[i] valid for 1 <= i < cnt
    int iters = (cnt + 7) >> 3;
    for (int it = 0; it < iters; it++) {
        int i0 = it * 8 + g * 2, i1 = i0 + 1;
        bool v0 = i0 < cnt, v1 = i1 < cnt;
        int s0 = (v0 && i0 > 0) ? csrc[i0] : n;
        int s1 = v1 ? csrc[i1] : n;
        const float4* a40 = (const float4*)(g_xl1 + s0 * 64 + s * 8);
        const float4* a41 = (const float4*)(g_xl1 + s1 * 64 + s * 8);
        float4 a0A = a40[0], a0B = a40[1];
        float4 a1A = a41[0], a1B = a41[1];
        float t0 = atA.x * lrelu(a0A.x + xrA.x) + atA.y * lrelu(a0A.y + xrA.y) +
                   atA.z * lrelu(a0A.z + xrA.z) + atA.w * lrelu(a0A.w + xrA.w) +
                   atB.x * lrelu(a0B.x + xrB.x) + atB.y * lrelu(a0B.y + xrB.y) +
                   atB.z * lrelu(a0B.z + xrB.z) + atB.w * lrelu(a0B.w + xrB.w);
        float t1 = atA.x * lrelu(a1A.x + xrA.x) + atA.y * lrelu(a1A.y + xrA.y) +
                   atA.z * lrelu(a1A.z + xrA.z) + atA.w * lrelu(a1A.w + xrA.w) +
                   atB.x * lrelu(a1B.x + xrB.x) + atB.y * lrelu(a1B.y + xrB.y) +
                   atB.z * lrelu(a1B.z + xrB.z) + atB.w * lrelu(a1B.w + xrB.w);
        t0 += __shfl_xor_sync(0xffffffffu, t0, 1);   // head reduce
        t1 += __shfl_xor_sync(0xffffffffu, t1, 1);
        float p0 = v0 ? __expf(t0) : 0.f;
        float p1 = v1 ? __expf(t1) : 0.f;
        den += p0 + p1;
        acc[0] += p0 * a0A.x + p1 * a1A.x;
        acc[1] += p0 * a0A.y + p1 * a1A.y;
        acc[2] += p0 * a0A.z + p1 * a1A.z;
        acc[3] += p0 * a0A.w + p1 * a1A.w;
        acc[4] += p0 * a0B.x + p1 * a1B.x;
        acc[5] += p0 * a0B.y + p1 * a1B.y;
        acc[6] += p0 * a0B.z + p1 * a1B.z;
        acc[7] += p0 * a0B.w + p1 * a1B.w;
    }
#pragma unroll
    for (int d = 8; d <= 16; d <<= 1) {
        den += __shfl_xor_sync(0xffffffffu, den, d);
#pragma unroll
        for (int j = 0; j < 8; j++) acc[j] += __shfl_xor_sync(0xffffffffu, acc[j], d);
    }
    if (g == 0) {
        float inv = 1.0f / (den + 1e-16f);
        const float4* b4 = (const float4*)(b1 + s * 8);
        float4 bA = b4[0], bB = b4[1];
        float4 vA, vB;
        vA.x = fmaxf(acc[0] * inv + bA.x, 0.f);
        vA.y = fmaxf(acc[1] * inv + bA.y, 0.f);
        vA.z = fmaxf(acc[2] * inv + bA.z, 0.f);
        vA.w = fmaxf(acc[3] * inv + bA.w, 0.f);
        vB.x = fmaxf(acc[4] * inv + bB.x, 0.f);
        vB.y = fmaxf(acc[5] * inv + bB.y, 0.f);
        vB.z = fmaxf(acc[6] * inv + bB.z, 0.f);
        vB.w = fmaxf(acc[7] * inv + bB.w, 0.f);
        float4* o4 = (float4*)(g_h1 + n * 64 + s * 8);
        o4[0] = vA; o4[1] = vB;
    }
}

// layer-2 agg: 1 head x 64 dims; 8-lane group reduce; fused mean-pool + count.
// Last reader of g_deg -> resets it for the next call.
__global__ __launch_bounds__(256) void k_agg2(const float* __restrict__ att,
                                              const float* __restrict__ b2,
                                              const void* __restrict__ batch) {
    int warp = (blockIdx.x * 256 + threadIdx.x) >> 5;
    if (warp >= NN) return;
    int lane = threadIdx.x & 31;
    int g = lane >> 3, s = lane & 7;
    int n = warp;

    const float4* xr4 = (const float4*)(g_xr2 + n * 64 + s * 8);
    float4 xrA = xr4[0], xrB = xr4[1];
    float4 atA = ((const float4*)(att + s * 8))[0];
    float4 atB = ((const float4*)(att + s * 8))[1];

    float den = 0.f;
    float acc[8] = {0.f, 0.f, 0.f, 0.f, 0.f, 0.f, 0.f, 0.f};

    int cntE = g_deg[n]; if (cntE > CAP) cntE = CAP;
    if (lane == 0) g_deg[n] = 0;           // reset for next call's fill
    int cnt = cntE + 1;
    const int* csrc = g_csrc + n * CAP - 1;
    int iters = (cnt + 7) >> 3;
    for (int it = 0; it < iters; it++) {
        int i0 = it * 8 + g * 2, i1 = i0 + 1;
        bool v0 = i0 < cnt, v1 = i1 < cnt;
        int s0 = (v0 && i0 > 0) ? csrc[i0] : n;
        int s1 = v1 ? csrc[i1] : n;
        const float4* a40 = (const float4*)(g_xl2 + s0 * 64 + s * 8);
        const float4* a41 = (const float4*)(g_xl2 + s1 * 64 + s * 8);
        float4 a0A = a40[0], a0B = a40[1];
        float4 a1A = a41[0], a1B = a41[1];
        float t0 = atA.x * lrelu(a0A.x + xrA.x) + atA.y * lrelu(a0A.y + xrA.y) +
                   atA.z * lrelu(a0A.z + xrA.z) + atA.w * lrelu(a0A.w + xrA.w) +
                   atB.x * lrelu(a0B.x + xrB.x) + atB.y * lrelu(a0B.y + xrB.y) +
                   atB.z * lrelu(a0B.z + xrB.z) + atB.w * lrelu(a0B.w + xrB.w);
        float t1 = atA.x * lrelu(a1A.x + xrA.x) + atA.y * lrelu(a1A.y + xrA.y) +
                   atA.z * lrelu(a1A.z + xrA.z) + atA.w * lrelu(a1A.w + xrA.w) +
                   atB.x * lrelu(a1B.x + xrB.x) + atB.y * lrelu(a1B.y + xrB.y) +
                   atB.z * lrelu(a1B.z + xrB.z) + atB.w * lrelu(a1B.w + xrB.w);
        t0 += __shfl_xor_sync(0xffffffffu, t0, 1);
        t1 += __shfl_xor_sync(0xffffffffu, t1, 1);
        t0 += __shfl_xor_sync(0xffffffffu, t0, 2);
        t1 += __shfl_xor_sync(0xffffffffu, t1, 2);
        t0 += __shfl_xor_sync(0xffffffffu, t0, 4);
        t1 += __shfl_xor_sync(0xffffffffu, t1, 4);
        float p0 = v0 ? __expf(t0) : 0.f;
        float p1 = v1 ? __expf(t1) : 0.f;
        den += p0 + p1;
        acc[0] += p0 * a0A.x + p1 * a1A.x;
        acc[1] += p0 * a0A.y + p1 * a1A.y;
        acc[2] += p0 * a0A.z + p1 * a1A.z;
        acc[3] += p0 * a0A.w + p1 * a1A.w;
        acc[4] += p0 * a0B.x + p1 * a1B.x;
        acc[5] += p0 * a0B.y + p1 * a1B.y;
        acc[6] += p0 * a0B.z + p1 * a1B.z;
        acc[7] += p0 * a0B.w + p1 * a1B.w;
    }
#pragma unroll
    for (int d = 8; d <= 16; d <<= 1) {
        den += __shfl_xor_sync(0xffffffffu, den, d);
#pragma unroll
        for (int j = 0; j < 8; j++) acc[j] += __shfl_xor_sync(0xffffffffu, acc[j], d);
    }
    if (g == 0) {
        float inv = 1.0f / (den + 1e-16f);
        const float4* b4 = (const float4*)(b2 + s * 8);
        float4 bA = b4[0], bB = b4[1];
        float v0f = fmaxf(acc[0] * inv + bA.x, 0.f);
        float v1f = fmaxf(acc[1] * inv + bA.y, 0.f);
        float v2f = fmaxf(acc[2] * inv + bA.z, 0.f);
        float v3f = fmaxf(acc[3] * inv + bA.w, 0.f);
        float v4f = fmaxf(acc[4] * inv + bB.x, 0.f);
        float v5f = fmaxf(acc[5] * inv + bB.y, 0.f);
        float v6f = fmaxf(acc[6] * inv + bB.z, 0.f);
        float v7f = fmaxf(acc[7] * inv + bB.w, 0.f);
        int gid = ldidx(batch, n, g_b64);
        float* dst = g_pool + gid * 64 + s * 8;
        redAdd4(dst + 0, v0f, v1f, v2f, v3f);
        redAdd4(dst + 4, v4f, v5f, v6f, v7f);
        if (s == 0) atomicAdd(&g_cnt[gid], 1.0f);
    }
}

// predictor: out[g] = (pool[g]/max(cnt,1)) . Wp + bp
__global__ void k_pred(const float* __restrict__ Wp, const float* __restrict__ bp,
                       float* __restrict__ out) {
    int g = blockIdx.x * blockDim.x + threadIdx.x;
    if (g >= NG) return;
    float s = 0.f;
#pragma unroll
    for (int c = 0; c < 64; c++) s += g_pool[g * 64 + c] * Wp[c];
    out[g] = s / fmaxf(g_cnt[g], 1.0f) + bp[0];
}

// ---------------- launch --------------------------------------------------------
extern "C" void kernel_launch(void* const* d_in, const int* in_sizes, int n_in,
                              void* d_out, int out_size) {
    const float* x    = (const float*)d_in[0];
    const void*  ei   = d_in[1];
    const void*  batch= d_in[2];
    const float* W1l  = (const float*)d_in[3];
    const float* W1r  = (const float*)d_in[4];
    const float* att1 = (const float*)d_in[5];
    const float* b1   = (const float*)d_in[6];
    const float* W2l  = (const float*)d_in[7];
    const float* W2r  = (const float*)d_in[8];
    const float* att2 = (const float*)d_in[9];
    const float* b2   = (const float*)d_in[10];
    const float* Wp   = (const float*)d_in[11];
    const float* bp   = (const float*)d_in[12];
    float* out = (float*)d_out;

    const int T = 256;
    k_pre<<<GEMM1_BLOCKS + FILL_BLOCKS, T>>>(x, W1l, W1r, ei, (const int*)batch);
    k_agg1<<<(NN + 7) / 8, T>>>(att1, b1);
    k_gemm2<<<(NN + G2M - 1) / G2M, 256>>>(W2l, W2r);
    k_agg2<<<(NN + 7) / 8, T>>>(att2, b2, batch);       // launch #4 -> profiled
    k_pred<<<(NG + T - 1) / T, T>>>(Wp, bp, out);
}

// round 16
// speedup vs baseline: 1.1865x; 1.1299x over previous
#include <cuda_runtime.h>
#include <cuda_bf16.h>

#define NN 50000
#define NE 1600000
#define NG 512
#define NEG_SLOPE 0.2f
#define SCAN_BLOCKS 196   // 196*256 = 50176 >= NN
#define SCAN_THREADS (SCAN_BLOCKS * 256)
#define GEMM1_BLOCKS 12500      // NN*64 / 256
#define COUNT_BLOCKS 3125       // NE / (256*2)
#define G2M 128                 // nodes per gemm2 block (512 threads)

// ---------------- scratch (device globals; no dynamic alloc allowed) ----------
__device__ int g_deg[SCAN_THREADS];   // zeroed by scanfill each call (static init 0)
__device__ int g_agg[SCAN_BLOCKS];
__device__ int g_ctr1;
__device__ int g_ctr2;
__device__ int g_off[NN + 1];
__device__ int g_cur[NN];
__device__ int g_csrc[NE];

__device__ float g_xl1[NN * 64];
__device__ float g_xr1[NN * 64];
__device__ float g_h1[NN * 64];
__device__ float g_xl2[NN * 64];
__device__ float g_xr2[NN * 64];
__device__ float g_pool[NG * 64];
__device__ float g_cnt[NG];
__device__ int g_ei64;   // 1 if edge_index is int64
__device__ int g_b64;    // 1 if batch is int64

// ---------------- helpers -----------------------------------------------------
__device__ __forceinline__ float lrelu(float v) {
    return fmaxf(v, NEG_SLOPE * v);
}
__device__ __forceinline__ int ldidx(const void* p, long long i, int is64) {
    return is64 ? (int)((const long long*)p)[i] : ((const int*)p)[i];
}
__device__ __forceinline__ void redAdd4(float* p, float a, float b, float c, float d) {
    asm volatile("red.global.add.v4.f32 [%0], {%1, %2, %3, %4};"
                 :: "l"(p), "f"(a), "f"(b), "f"(c), "f"(d) : "memory");
}
#define FMA2(d, a, b) asm("fma.rn.f32x2 %0, %1, %2, %0;" : "+l"(d) : "l"(a), "l"(b))
#define DUP2(d, f) asm("mov.b64 %0, {%1, %1};" : "=l"(d) : "r"(__float_as_uint(f)))

// ---- k_pre: zero scratch + dtype detect + layer-1 transform + degree count ----
__global__ void k_pre(const float* __restrict__ x,
                      const float* __restrict__ Wl,
                      const float* __restrict__ Wr,
                      const void* __restrict__ ei,
                      const int* __restrict__ batch) {
    int tid = threadIdx.x;
    if (blockIdx.x >= GEMM1_BLOCKS) {
        __shared__ int sh_is64;
        if (tid < 32) {
            const int* e32 = (const int*)ei;
            int v = e32[2 * tid + 1] | e32[2 * (tid + 32) + 1];
            int any = __any_sync(0xffffffffu, v != 0);
            if (tid == 0) sh_is64 = any ? 0 : 1;
        }
        __syncthreads();
        int is64 = sh_is64;
        long long j = (long long)(blockIdx.x - GEMM1_BLOCKS) * 256 + tid;
        int d0, d1;
        if (is64) {
            longlong2 dp = ((const longlong2*)((const long long*)ei + NE))[j];
            d0 = (int)dp.x; d1 = (int)dp.y;
        } else {
            int2 dp = ((const int2*)((const int*)ei + NE))[j];
            d0 = dp.x; d1 = dp.y;
        }
        atomicAdd(&g_deg[d0], 1);
        atomicAdd(&g_deg[d1], 1);
        return;
    }

    int idx = blockIdx.x * 256 + tid;
    if (idx < NG * 64) g_pool[idx] = 0.f;
    if (idx < NG) g_cnt[idx] = 0.f;
    if (idx == 0) { g_ctr1 = 0; g_ctr2 = 0; }

    if (blockIdx.x == 0) {
        if (tid < 32) {
            const int* e32 = (const int*)ei;
            int v = e32[2 * tid + 1] | e32[2 * (tid + 32) + 1];
            int any = __any_sync(0xffffffffu, v != 0);
            if (tid == 0) g_ei64 = any ? 0 : 1;
        } else if (tid < 64) {
            int j = tid - 32;
            int v = batch[NN - 1 - 2 * j] | batch[NN - 1 - 2 * (j + 32)];
            int any = __any_sync(0xffffffffu, v != 0);
            if (tid == 32) g_b64 = any ? 0 : 1;
        }
    }

    int n = idx >> 6, c = idx & 63;
    float x0 = x[n * 5 + 0], x1 = x[n * 5 + 1], x2 = x[n * 5 + 2];
    float x3 = x[n * 5 + 3], x4 = x[n * 5 + 4];
    g_xl1[idx] = x0 * Wl[c] + x1 * Wl[64 + c] + x2 * Wl[128 + c] +
                 x3 * Wl[192 + c] + x4 * Wl[256 + c];
    g_xr1[idx] = x0 * Wr[c] + x1 * Wr[64 + c] + x2 * Wr[128 + c] +
                 x3 * Wr[192 + c] + x4 * Wr[256 + c];
}

// ---- fused CSR: block scans + grid-sync + offsets + grid-sync + 4-edge fill ----
__global__ __launch_bounds__(256) void k_scanfill(const void* __restrict__ ei) {
    __shared__ int sh[256];
    __shared__ int shw[8];
    __shared__ int sh_base;
    int tid = threadIdx.x, b = blockIdx.x;
    int i = b * 256 + tid;
    int v = g_deg[i];
    g_deg[i] = 0;               // reset for next call's counting (k_pre)

    sh[tid] = v;
    __syncthreads();
#pragma unroll
    for (int d = 1; d < 256; d <<= 1) {
        int a = sh[tid];
        int add = (tid >= d) ? sh[tid - d] : 0;
        __syncthreads();
        sh[tid] = a + add;
        __syncthreads();
    }
    int incl = sh[tid];
    if (tid == 255) g_agg[b] = incl;
    __syncthreads();

    if (tid == 0) {
        __threadfence();
        atomicAdd(&g_ctr1, 1);
        while (atomicAdd(&g_ctr1, 0) < SCAN_BLOCKS) __nanosleep(64);
        __threadfence();
    }
    __syncthreads();

    int a = (tid < b) ? g_agg[tid] : 0;
#pragma unroll
    for (int d = 16; d >= 1; d >>= 1) a += __shfl_xor_sync(0xffffffffu, a, d);
    if ((tid & 31) == 0) shw[tid >> 5] = a;
    __syncthreads();
    if (tid == 0) {
        int s = 0;
#pragma unroll
        for (int w = 0; w < 8; w++) s += shw[w];
        sh_base = s;
    }
    __syncthreads();

    int off = sh_base + incl - v;
    if (i < NN) { g_off[i] = off; g_cur[i] = off; }
    if (i == 0) g_off[NN] = NE;

    __syncthreads();
    if (tid == 0) {
        __threadfence();
        atomicAdd(&g_ctr2, 1);
        while (atomicAdd(&g_ctr2, 0) < SCAN_BLOCKS) __nanosleep(64);
        __threadfence();
    }
    __syncthreads();

    // 4 edges per thread-iteration: 4 independent atomic->store chains
    int is64 = g_ei64;
    for (long long base = (long long)i * 4; base < NE;
         base += (long long)SCAN_THREADS * 4) {
        int s0, s1, s2, s3, d0, d1, d2, d3;
        if (is64) {
            const long long* e64 = (const long long*)ei;
            longlong2 sa = *(const longlong2*)(e64 + base);
            longlong2 sb = *(const longlong2*)(e64 + base + 2);
            longlong2 da = *(const longlong2*)(e64 + NE + base);
            longlong2 db = *(const longlong2*)(e64 + NE + base + 2);
            s0 = (int)sa.x; s1 = (int)sa.y; s2 = (int)sb.x; s3 = (int)sb.y;
            d0 = (int)da.x; d1 = (int)da.y; d2 = (int)db.x; d3 = (int)db.y;
        } else {
            const int* e32 = (const int*)ei;
            int4 sp = *(const int4*)(e32 + base);
            int4 dp = *(const int4*)(e32 + NE + base);
            s0 = sp.x; s1 = sp.y; s2 = sp.z; s3 = sp.w;
            d0 = dp.x; d1 = dp.y; d2 = dp.z; d3 = dp.w;
        }
        int a0 = atomicAdd(&g_cur[d0], 1);
        int a1 = atomicAdd(&g_cur[d1], 1);
        int a2 = atomicAdd(&g_cur[d2], 1);
        int a3 = atomicAdd(&g_cur[d3], 1);
        g_csrc[a0] = s0;
        g_csrc[a1] = s1;
        g_csrc[a2] = s2;
        g_csrc[a3] = s3;
    }
}

// ------- layer-2 transform: tiled GEMM, 512 threads / 128 nodes per block -------
__global__ __launch_bounds__(512) void k_gemm2(const float* __restrict__ Wl,
                                               const float* __restrict__ Wr) {
    __shared__ float sX[64][G2M];    // 32 KB, [k][node]
    __shared__ float sW[64][128];    // 32 KB, [k][col]
    int tid = threadIdx.x;
    int nbase = blockIdx.x * G2M;

    for (int i = tid; i < 4096; i += 512) {
        int k = i >> 6, c = i & 63;
        sW[k][c] = Wl[i];
        sW[k][64 + c] = Wr[i];
    }
    for (int i = tid; i < G2M * 16; i += 512) {
        int node = i & (G2M - 1), f4 = i >> 7;
        int n = nbase + node;
        float4 v = make_float4(0.f, 0.f, 0.f, 0.f);
        if (n < NN) v = ((const float4*)(g_h1 + n * 64))[f4];
        sX[f4 * 4 + 0][node] = v.x;
        sX[f4 * 4 + 1][node] = v.y;
        sX[f4 * 4 + 2][node] = v.z;
        sX[f4 * 4 + 3][node] = v.w;
    }
    __syncthreads();

    int tr = tid >> 5;          // 16 node groups x 8 nodes = 128
    int tc = tid & 31;
    int nrow = tr * 8;
    unsigned long long accl[8] = {0,0,0,0,0,0,0,0};
    unsigned long long accr[8] = {0,0,0,0,0,0,0,0};

#pragma unroll 2
    for (int k = 0; k < 64; k++) {
        float4 xa = *(const float4*)&sX[k][nrow];
        float4 xb = *(const float4*)&sX[k][nrow + 4];
        unsigned long long wl = *(const unsigned long long*)&sW[k][tc * 2];
        unsigned long long wr = *(const unsigned long long*)&sW[k][64 + tc * 2];
        unsigned long long xx;
        DUP2(xx, xa.x); FMA2(accl[0], xx, wl); FMA2(accr[0], xx, wr);
        DUP2(xx, xa.y); FMA2(accl[1], xx, wl); FMA2(accr[1], xx, wr);
        DUP2(xx, xa.z); FMA2(accl[2], xx, wl); FMA2(accr[2], xx, wr);
        DUP2(xx, xa.w); FMA2(accl[3], xx, wl); FMA2(accr[3], xx, wr);
        DUP2(xx, xb.x); FMA2(accl[4], xx, wl); FMA2(accr[4], xx, wr);
        DUP2(xx, xb.y); FMA2(accl[5], xx, wl); FMA2(accr[5], xx, wr);
        DUP2(xx, xb.z); FMA2(accl[6], xx, wl); FMA2(accr[6], xx, wr);
        DUP2(xx, xb.w); FMA2(accl[7], xx, wl); FMA2(accr[7], xx, wr);
    }

#pragma unroll
    for (int j = 0; j < 8; j++) {
        int n = nbase + nrow + j;
        if (n < NN) {
            *(unsigned long long*)(g_xl2 + n * 64 + tc * 2) = accl[j];
            *(unsigned long long*)(g_xr2 + n * 64 + tc * 2) = accr[j];
        }
    }
}

// ------- aggregation: warp per dst, 4 groups x 2 edges, direct exp (R12) --------

// layer-1: 4 heads x 16 dims. sublane s owns dims [8s,8s+8) (head = s>>1).
__global__ __launch_bounds__(256) void k_agg1(const float* __restrict__ att,
                                              const float* __restrict__ b1) {
    int warp = (blockIdx.x * 256 + threadIdx.x) >> 5;
    if (warp >= NN) return;
    int lane = threadIdx.x & 31;
    int g = lane >> 3, s = lane & 7;
    int n = warp;

    const float4* xr4 = (const float4*)(g_xr1 + n * 64 + s * 8);
    float4 xrA = xr4[0], xrB = xr4[1];
    float4 atA = ((const float4*)(att + s * 8))[0];
    float4 atB = ((const float4*)(att + s * 8))[1];

    float den = 0.f;
    float acc[8] = {0.f, 0.f, 0.f, 0.f, 0.f, 0.f, 0.f, 0.f};

    int k0 = g_off[n];
    int cnt = g_off[n + 1] - k0 + 1;       // edges + self loop
    const int* csrc = g_csrc + k0 - 1;     // csrc[i] valid for 1 <= i < cnt
    int iters = (cnt + 7) >> 3;
    for (int it = 0; it < iters; it++) {
        int i0 = it * 8 + g * 2, i1 = i0 + 1;
        bool v0 = i0 < cnt, v1 = i1 < cnt;
        int s0 = (v0 && i0 > 0) ? csrc[i0] : n;
        int s1 = v1 ? csrc[i1] : n;
        const float4* a40 = (const float4*)(g_xl1 + s0 * 64 + s * 8);
        const float4* a41 = (const float4*)(g_xl1 + s1 * 64 + s * 8);
        float4 a0A = a40[0], a0B = a40[1];
        float4 a1A = a41[0], a1B = a41[1];
        float t0 = atA.x * lrelu(a0A.x + xrA.x) + atA.y * lrelu(a0A.y + xrA.y) +
                   atA.z * lrelu(a0A.z + xrA.z) + atA.w * lrelu(a0A.w + xrA.w) +
                   atB.x * lrelu(a0B.x + xrB.x) + atB.y * lrelu(a0B.y + xrB.y) +
                   atB.z * lrelu(a0B.z + xrB.z) + atB.w * lrelu(a0B.w + xrB.w);
        float t1 = atA.x * lrelu(a1A.x + xrA.x) + atA.y * lrelu(a1A.y + xrA.y) +
                   atA.z * lrelu(a1A.z + xrA.z) + atA.w * lrelu(a1A.w + xrA.w) +
                   atB.x * lrelu(a1B.x + xrB.x) + atB.y * lrelu(a1B.y + xrB.y) +
                   atB.z * lrelu(a1B.z + xrB.z) + atB.w * lrelu(a1B.w + xrB.w);
        t0 += __shfl_xor_sync(0xffffffffu, t0, 1);   // head reduce
        t1 += __shfl_xor_sync(0xffffffffu, t1, 1);
        float p0 = v0 ? __expf(t0) : 0.f;
        float p1 = v1 ? __expf(t1) : 0.f;
        den += p0 + p1;
        acc[0] += p0 * a0A.x + p1 * a1A.x;
        acc[1] += p0 * a0A.y + p1 * a1A.y;
        acc[2] += p0 * a0A.z + p1 * a1A.z;
        acc[3] += p0 * a0A.w + p1 * a1A.w;
        acc[4] += p0 * a0B.x + p1 * a1B.x;
        acc[5] += p0 * a0B.y + p1 * a1B.y;
        acc[6] += p0 * a0B.z + p1 * a1B.z;
        acc[7] += p0 * a0B.w + p1 * a1B.w;
    }
#pragma unroll
    for (int d = 8; d <= 16; d <<= 1) {
        den += __shfl_xor_sync(0xffffffffu, den, d);
#pragma unroll
        for (int j = 0; j < 8; j++) acc[j] += __shfl_xor_sync(0xffffffffu, acc[j], d);
    }
    if (g == 0) {
        float inv = 1.0f / (den + 1e-16f);
        const float4* b4 = (const float4*)(b1 + s * 8);
        float4 bA = b4[0], bB = b4[1];
        float4 vA, vB;
        vA.x = fmaxf(acc[0] * inv + bA.x, 0.f);
        vA.y = fmaxf(acc[1] * inv + bA.y, 0.f);
        vA.z = fmaxf(acc[2] * inv + bA.z, 0.f);
        vA.w = fmaxf(acc[3] * inv + bA.w, 0.f);
        vB.x = fmaxf(acc[4] * inv + bB.x, 0.f);
        vB.y = fmaxf(acc[5] * inv + bB.y, 0.f);
        vB.z = fmaxf(acc[6] * inv + bB.z, 0.f);
        vB.w = fmaxf(acc[7] * inv + bB.w, 0.f);
        float4* o4 = (float4*)(g_h1 + n * 64 + s * 8);
        o4[0] = vA; o4[1] = vB;
    }
}

// layer-2 agg: 1 head x 64 dims; 8-lane group reduce; fused mean-pool + count.
__global__ __launch_bounds__(256) void k_agg2(const float* __restrict__ att,
                                              const float* __restrict__ b2,
                                              const void* __restrict__ batch) {
    int warp = (blockIdx.x * 256 + threadIdx.x) >> 5;
    if (warp >= NN) return;
    int lane = threadIdx.x & 31;
    int g = lane >> 3, s = lane & 7;
    int n = warp;

    const float4* xr4 = (const float4*)(g_xr2 + n * 64 + s * 8);
    float4 xrA = xr4[0], xrB = xr4[1];
    float4 atA = ((const float4*)(att + s * 8))[0];
    float4 atB = ((const float4*)(att + s * 8))[1];

    float den = 0.f;
    float acc[8] = {0.f, 0.f, 0.f, 0.f, 0.f, 0.f, 0.f, 0.f};

    int k0 = g_off[n];
    int cnt = g_off[n + 1] - k0 + 1;
    const int* csrc = g_csrc + k0 - 1;
    int iters = (cnt + 7) >> 3;
    for (int it = 0; it < iters; it++) {
        int i0 = it * 8 + g * 2, i1 = i0 + 1;
        bool v0 = i0 < cnt, v1 = i1 < cnt;
        int s0 = (v0 && i0 > 0) ? csrc[i0] : n;
        int s1 = v1 ? csrc[i1] : n;
        const float4* a40 = (const float4*)(g_xl2 + s0 * 64 + s * 8);
        const float4* a41 = (const float4*)(g_xl2 + s1 * 64 + s * 8);
        float4 a0A = a40[0], a0B = a40[1];
        float4 a1A = a41[0], a1B = a41[1];
        float t0 = atA.x * lrelu(a0A.x + xrA.x) + atA.y * lrelu(a0A.y + xrA.y) +
                   atA.z * lrelu(a0A.z + xrA.z) + atA.w * lrelu(a0A.w + xrA.w) +
                   atB.x * lrelu(a0B.x + xrB.x) + atB.y * lrelu(a0B.y + xrB.y) +
                   atB.z * lrelu(a0B.z + xrB.z) + atB.w * lrelu(a0B.w + xrB.w);
        float t1 = atA.x * lrelu(a1A.x + xrA.x) + atA.y * lrelu(a1A.y + xrA.y) +
                   atA.z * lrelu(a1A.z + xrA.z) + atA.w * lrelu(a1A.w + xrA.w) +
                   atB.x * lrelu(a1B.x + xrB.x) + atB.y * lrelu(a1B.y + xrB.y) +
                   atB.z * lrelu(a1B.z + xrB.z) + atB.w * lrelu(a1B.w + xrB.w);
        t0 += __shfl_xor_sync(0xffffffffu, t0, 1);
        t1 += __shfl_xor_sync(0xffffffffu, t1, 1);
        t0 += __shfl_xor_sync(0xffffffffu, t0, 2);
        t1 += __shfl_xor_sync(0xffffffffu, t1, 2);
        t0 += __shfl_xor_sync(0xffffffffu, t0, 4);
        t1 += __shfl_xor_sync(0xffffffffu, t1, 4);
        float p0 = v0 ? __expf(t0) : 0.f;
        float p1 = v1 ? __expf(t1) : 0.f;
        den += p0 + p1;
        acc[0] += p0 * a0A.x + p1 * a1A.x;
        acc[1] += p0 * a0A.y + p1 * a1A.y;
        acc[2] += p0 * a0A.z + p1 * a1A.z;
        acc[3] += p0 * a0A.w + p1 * a1A.w;
        acc[4] += p0 * a0B.x + p1 * a1B.x;
        acc[5] += p0 * a0B.y + p1 * a1B.y;
        acc[6] += p0 * a0B.z + p1 * a1B.z;
        acc[7] += p0 * a0B.w + p1 * a1B.w;
    }
#pragma unroll
    for (int d = 8; d <= 16; d <<= 1) {
        den += __shfl_xor_sync(0xffffffffu, den, d);
#pragma unroll
        for (int j = 0; j < 8; j++) acc[j] += __shfl_xor_sync(0xffffffffu, acc[j], d);
    }
    if (g == 0) {
        float inv = 1.0f / (den + 1e-16f);
        const float4* b4 = (const float4*)(b2 + s * 8);
        float4 bA = b4[0], bB = b4[1];
        float v0f = fmaxf(acc[0] * inv + bA.x, 0.f);
        float v1f = fmaxf(acc[1] * inv + bA.y, 0.f);
        float v2f = fmaxf(acc[2] * inv + bA.z, 0.f);
        float v3f = fmaxf(acc[3] * inv + bA.w, 0.f);
        float v4f = fmaxf(acc[4] * inv + bB.x, 0.f);
        float v5f = fmaxf(acc[5] * inv + bB.y, 0.f);
        float v6f = fmaxf(acc[6] * inv + bB.z, 0.f);
        float v7f = fmaxf(acc[7] * inv + bB.w, 0.f);
        int gid = ldidx(batch, n, g_b64);
        float* dst = g_pool + gid * 64 + s * 8;
        redAdd4(dst + 0, v0f, v1f, v2f, v3f);
        redAdd4(dst + 4, v4f, v5f, v6f, v7f);
        if (s == 0) atomicAdd(&g_cnt[gid], 1.0f);
    }
}

// predictor: out[g] = (pool[g]/max(cnt,1)) . Wp + bp
__global__ void k_pred(const float* __restrict__ Wp, const float* __restrict__ bp,
                       float* __restrict__ out) {
    int g = blockIdx.x * blockDim.x + threadIdx.x;
    if (g >= NG) return;
    float s = 0.f;
#pragma unroll
    for (int c = 0; c < 64; c++) s += g_pool[g * 64 + c] * Wp[c];
    out[g] = s / fmaxf(g_cnt[g], 1.0f) + bp[0];
}

// ---------------- launch --------------------------------------------------------
extern "C" void kernel_launch(void* const* d_in, const int* in_sizes, int n_in,
                              void* d_out, int out_size) {
    const float* x    = (const float*)d_in[0];
    const void*  ei   = d_in[1];
    const void*  batch= d_in[2];
    const float* W1l  = (const float*)d_in[3];
    const float* W1r  = (const float*)d_in[4];
    const float* att1 = (const float*)d_in[5];
    const float* b1   = (const float*)d_in[6];
    const float* W2l  = (const float*)d_in[7];
    const float* W2r  = (const float*)d_in[8];
    const float* att2 = (const float*)d_in[9];
    const float* b2   = (const float*)d_in[10];
    const float* Wp   = (const float*)d_in[11];
    const float* bp   = (const float*)d_in[12];
    float* out = (float*)d_out;

    const int T = 256;
    k_pre<<<GEMM1_BLOCKS + COUNT_BLOCKS, T>>>(x, W1l, W1r, ei, (const int*)batch);
    k_scanfill<<<SCAN_BLOCKS, T>>>(ei);
    k_agg1<<<(NN + 7) / 8, T>>>(att1, b1);
    k_gemm2<<<(NN + G2M - 1) / G2M, 512>>>(W2l, W2r);   // launch #4 -> profiled
    k_agg2<<<(NN + 7) / 8, T>>>(att2, b2, batch);
    k_pred<<<(NG + T - 1) / T, T>>>(Wp, bp, out);
}

// round 17
// speedup vs baseline: 1.2055x; 1.0161x over previous
#include <cuda_runtime.h>
#include <cuda_bf16.h>

#define NN 50000
#define NE 1600000
#define NG 512
#define NEG_SLOPE 0.2f
#define SCAN_BLOCKS 196   // 196*256 = 50176 >= NN
#define SCAN_THREADS (SCAN_BLOCKS * 256)
#define GEMM1_BLOCKS 12500      // NN*64 / 256
#define COUNT_BLOCKS 3125       // NE / (256*2)
#define G2M 128                 // nodes per gemm2 block (512 threads)
#define NTOT (NE + NN)          // CSR entries incl. self loops

// ---------------- scratch (device globals; no dynamic alloc allowed) ----------
__device__ int g_deg[SCAN_THREADS];   // zeroed by scanfill each call (static init 0)
__device__ int g_agg[SCAN_BLOCKS];
__device__ int g_ctr1;
__device__ int g_ctr2;
__device__ int g_off[NN + 1];
__device__ int g_cur[NN];
__device__ int g_csrc[NTOT];

__device__ float g_xl1[NN * 64];
__device__ float g_xr1[NN * 64];
__device__ float g_h1[NN * 64];
__device__ float g_xl2[NN * 64];
__device__ float g_xr2[NN * 64];
__device__ float g_pool[NG * 64];
__device__ float g_cnt[NG];
__device__ int g_ei64;   // 1 if edge_index is int64
__device__ int g_b64;    // 1 if batch is int64

// ---------------- helpers -----------------------------------------------------
__device__ __forceinline__ float lrelu(float v) {
    return fmaxf(v, NEG_SLOPE * v);
}
__device__ __forceinline__ int ldidx(const void* p, long long i, int is64) {
    return is64 ? (int)((const long long*)p)[i] : ((const int*)p)[i];
}
__device__ __forceinline__ void redAdd4(float* p, float a, float b, float c, float d) {
    asm volatile("red.global.add.v4.f32 [%0], {%1, %2, %3, %4};"
                 :: "l"(p), "f"(a), "f"(b), "f"(c), "f"(d) : "memory");
}
#define FMA2(d, a, b) asm("fma.rn.f32x2 %0, %1, %2, %0;" : "+l"(d) : "l"(a), "l"(b))
#define DUP2(d, f) asm("mov.b64 %0, {%1, %1};" : "=l"(d) : "r"(__float_as_uint(f)))

// ---- k_pre: zero scratch + dtype detect + layer-1 transform + degree count ----
__global__ void k_pre(const float* __restrict__ x,
                      const float* __restrict__ Wl,
                      const float* __restrict__ Wr,
                      const void* __restrict__ ei,
                      const int* __restrict__ batch) {
    int tid = threadIdx.x;
    if (blockIdx.x >= GEMM1_BLOCKS) {
        __shared__ int sh_is64;
        if (tid < 32) {
            const int* e32 = (const int*)ei;
            int v = e32[2 * tid + 1] | e32[2 * (tid + 32) + 1];
            int any = __any_sync(0xffffffffu, v != 0);
            if (tid == 0) sh_is64 = any ? 0 : 1;
        }
        __syncthreads();
        int is64 = sh_is64;
        long long j = (long long)(blockIdx.x - GEMM1_BLOCKS) * 256 + tid;
        int d0, d1;
        if (is64) {
            longlong2 dp = ((const longlong2*)((const long long*)ei + NE))[j];
            d0 = (int)dp.x; d1 = (int)dp.y;
        } else {
            int2 dp = ((const int2*)((const int*)ei + NE))[j];
            d0 = dp.x; d1 = dp.y;
        }
        atomicAdd(&g_deg[d0], 1);
        atomicAdd(&g_deg[d1], 1);
        return;
    }

    int idx = blockIdx.x * 256 + tid;
    if (idx < NG * 64) g_pool[idx] = 0.f;
    if (idx < NG) g_cnt[idx] = 0.f;
    if (idx == 0) { g_ctr1 = 0; g_ctr2 = 0; }

    if (blockIdx.x == 0) {
        if (tid < 32) {
            const int* e32 = (const int*)ei;
            int v = e32[2 * tid + 1] | e32[2 * (tid + 32) + 1];
            int any = __any_sync(0xffffffffu, v != 0);
            if (tid == 0) g_ei64 = any ? 0 : 1;
        } else if (tid < 64) {
            int j = tid - 32;
            int v = batch[NN - 1 - 2 * j] | batch[NN - 1 - 2 * (j + 32)];
            int any = __any_sync(0xffffffffu, v != 0);
            if (tid == 32) g_b64 = any ? 0 : 1;
        }
    }

    int n = idx >> 6, c = idx & 63;
    float x0 = x[n * 5 + 0], x1 = x[n * 5 + 1], x2 = x[n * 5 + 2];
    float x3 = x[n * 5 + 3], x4 = x[n * 5 + 4];
    g_xl1[idx] = x0 * Wl[c] + x1 * Wl[64 + c] + x2 * Wl[128 + c] +
                 x3 * Wl[192 + c] + x4 * Wl[256 + c];
    g_xr1[idx] = x0 * Wr[c] + x1 * Wr[64 + c] + x2 * Wr[128 + c] +
                 x3 * Wr[192 + c] + x4 * Wr[256 + c];
}

// ---- fused CSR (self-loop embedded at slot 0): scans + syncs + 4-edge fill -----
__global__ __launch_bounds__(256) void k_scanfill(const void* __restrict__ ei) {
    __shared__ int sh[256];
    __shared__ int shw[8];
    __shared__ int sh_base;
    int tid = threadIdx.x, b = blockIdx.x;
    int i = b * 256 + tid;
    int vdeg = g_deg[i];
    g_deg[i] = 0;               // reset for next call's counting (k_pre)
    int v = (i < NN) ? vdeg + 1 : 0;   // +1 slot for the self loop

    sh[tid] = v;
    __syncthreads();
#pragma unroll
    for (int d = 1; d < 256; d <<= 1) {
        int a = sh[tid];
        int add = (tid >= d) ? sh[tid - d] : 0;
        __syncthreads();
        sh[tid] = a + add;
        __syncthreads();
    }
    int incl = sh[tid];
    if (tid == 255) g_agg[b] = incl;
    __syncthreads();

    if (tid == 0) {
        __threadfence();
        atomicAdd(&g_ctr1, 1);
        while (atomicAdd(&g_ctr1, 0) < SCAN_BLOCKS) __nanosleep(64);
        __threadfence();
    }
    __syncthreads();

    int a = (tid < b) ? g_agg[tid] : 0;
#pragma unroll
    for (int d = 16; d >= 1; d >>= 1) a += __shfl_xor_sync(0xffffffffu, a, d);
    if ((tid & 31) == 0) shw[tid >> 5] = a;
    __syncthreads();
    if (tid == 0) {
        int s = 0;
#pragma unroll
        for (int w = 0; w < 8; w++) s += shw[w];
        sh_base = s;
    }
    __syncthreads();

    int off = sh_base + incl - v;   // exclusive
    if (i < NN) {
        g_off[i] = off;
        g_csrc[off] = i;            // self loop pre-stored at slot 0
        g_cur[i] = off + 1;
    }
    if (i == 0) g_off[NN] = NTOT;

    __syncthreads();
    if (tid == 0) {
        __threadfence();
        atomicAdd(&g_ctr2, 1);
        while (atomicAdd(&g_ctr2, 0) < SCAN_BLOCKS) __nanosleep(64);
        __threadfence();
    }
    __syncthreads();

    // 4 edges per thread-iteration: 4 independent atomic->store chains
    int is64 = g_ei64;
    for (long long base = (long long)i * 4; base < NE;
         base += (long long)SCAN_THREADS * 4) {
        int s0, s1, s2, s3, d0, d1, d2, d3;
        if (is64) {
            const long long* e64 = (const long long*)ei;
            longlong2 sa = *(const longlong2*)(e64 + base);
            longlong2 sb = *(const longlong2*)(e64 + base + 2);
            longlong2 da = *(const longlong2*)(e64 + NE + base);
            longlong2 db = *(const longlong2*)(e64 + NE + base + 2);
            s0 = (int)sa.x; s1 = (int)sa.y; s2 = (int)sb.x; s3 = (int)sb.y;
            d0 = (int)da.x; d1 = (int)da.y; d2 = (int)db.x; d3 = (int)db.y;
        } else {
            const int* e32 = (const int*)ei;
            int4 sp = *(const int4*)(e32 + base);
            int4 dp = *(const int4*)(e32 + NE + base);
            s0 = sp.x; s1 = sp.y; s2 = sp.z; s3 = sp.w;
            d0 = dp.x; d1 = dp.y; d2 = dp.z; d3 = dp.w;
        }
        int a0 = atomicAdd(&g_cur[d0], 1);
        int a1 = atomicAdd(&g_cur[d1], 1);
        int a2 = atomicAdd(&g_cur[d2], 1);
        int a3 = atomicAdd(&g_cur[d3], 1);
        g_csrc[a0] = s0;
        g_csrc[a1] = s1;
        g_csrc[a2] = s2;
        g_csrc[a3] = s3;
    }
}

// ------- layer-2 transform: tiled GEMM, 512 threads / 128 nodes per block -------
__global__ __launch_bounds__(512) void k_gemm2(const float* __restrict__ Wl,
                                               const float* __restrict__ Wr) {
    __shared__ float sX[64][G2M];    // 32 KB, [k][node]
    __shared__ float sW[64][128];    // 32 KB, [k][col]
    int tid = threadIdx.x;
    int nbase = blockIdx.x * G2M;

    for (int i = tid; i < 4096; i += 512) {
        int k = i >> 6, c = i & 63;
        sW[k][c] = Wl[i];
        sW[k][64 + c] = Wr[i];
    }
    for (int i = tid; i < G2M * 16; i += 512) {
        int node = i & (G2M - 1), f4 = i >> 7;
        int n = nbase + node;
        float4 v = make_float4(0.f, 0.f, 0.f, 0.f);
        if (n < NN) v = ((const float4*)(g_h1 + n * 64))[f4];
        sX[f4 * 4 + 0][node] = v.x;
        sX[f4 * 4 + 1][node] = v.y;
        sX[f4 * 4 + 2][node] = v.z;
        sX[f4 * 4 + 3][node] = v.w;
    }
    __syncthreads();

    int tr = tid >> 5;          // 16 node groups x 8 nodes = 128
    int tc = tid & 31;
    int nrow = tr * 8;
    unsigned long long accl[8] = {0,0,0,0,0,0,0,0};
    unsigned long long accr[8] = {0,0,0,0,0,0,0,0};

#pragma unroll 2
    for (int k = 0; k < 64; k++) {
        float4 xa = *(const float4*)&sX[k][nrow];
        float4 xb = *(const float4*)&sX[k][nrow + 4];
        unsigned long long wl = *(const unsigned long long*)&sW[k][tc * 2];
        unsigned long long wr = *(const unsigned long long*)&sW[k][64 + tc * 2];
        unsigned long long xx;
        DUP2(xx, xa.x); FMA2(accl[0], xx, wl); FMA2(accr[0], xx, wr);
        DUP2(xx, xa.y); FMA2(accl[1], xx, wl); FMA2(accr[1], xx, wr);
        DUP2(xx, xa.z); FMA2(accl[2], xx, wl); FMA2(accr[2], xx, wr);
        DUP2(xx, xa.w); FMA2(accl[3], xx, wl); FMA2(accr[3], xx, wr);
        DUP2(xx, xb.x); FMA2(accl[4], xx, wl); FMA2(accr[4], xx, wr);
        DUP2(xx, xb.y); FMA2(accl[5], xx, wl); FMA2(accr[5], xx, wr);
        DUP2(xx, xb.z); FMA2(accl[6], xx, wl); FMA2(accr[6], xx, wr);
        DUP2(xx, xb.w); FMA2(accl[7], xx, wl); FMA2(accr[7], xx, wr);
    }

#pragma unroll
    for (int j = 0; j < 8; j++) {
        int n = nbase + nrow + j;
        if (n < NN) {
            *(unsigned long long*)(g_xl2 + n * 64 + tc * 2) = accl[j];
            *(unsigned long long*)(g_xr2 + n * 64 + tc * 2) = accr[j];
        }
    }
}

// ------- aggregation: warp per dst, 4 groups x 2 edges, self-loop in CSR --------

// layer-1: 4 heads x 16 dims. sublane s owns dims [8s,8s+8) (head = s>>1).
__global__ __launch_bounds__(256) void k_agg1(const float* __restrict__ att,
                                              const float* __restrict__ b1) {
    int warp = (blockIdx.x * 256 + threadIdx.x) >> 5;
    if (warp >= NN) return;
    int lane = threadIdx.x & 31;
    int g = lane >> 3, s = lane & 7;
    int n = warp;

    const float4* xr4 = (const float4*)(g_xr1 + n * 64 + s * 8);
    float4 xrA = xr4[0], xrB = xr4[1];
    float4 atA = ((const float4*)(att + s * 8))[0];
    float4 atB = ((const float4*)(att + s * 8))[1];

    float den = 0.f;
    float acc[8] = {0.f, 0.f, 0.f, 0.f, 0.f, 0.f, 0.f, 0.f};

    int k0 = g_off[n];
    int cnt = g_off[n + 1] - k0;           // self loop included
    const int* csrc = g_csrc + k0;
    int iters = (cnt + 7) >> 3;
    for (int it = 0; it < iters; it++) {
        int i0 = it * 8 + g * 2, i1 = i0 + 1;
        bool v0 = i0 < cnt, v1 = i1 < cnt;
        int s0 = v0 ? csrc[i0] : n;
        int s1 = v1 ? csrc[i1] : n;
        const float4* a40 = (const float4*)(g_xl1 + s0 * 64 + s * 8);
        const float4* a41 = (const float4*)(g_xl1 + s1 * 64 + s * 8);
        float4 a0A = a40[0], a0B = a40[1];
        float4 a1A = a41[0], a1B = a41[1];
        float t0 = atA.x * lrelu(a0A.x + xrA.x) + atA.y * lrelu(a0A.y + xrA.y) +
                   atA.z * lrelu(a0A.z + xrA.z) + atA.w * lrelu(a0A.w + xrA.w) +
                   atB.x * lrelu(a0B.x + xrB.x) + atB.y * lrelu(a0B.y + xrB.y) +
                   atB.z * lrelu(a0B.z + xrB.z) + atB.w * lrelu(a0B.w + xrB.w);
        float t1 = atA.x * lrelu(a1A.x + xrA.x) + atA.y * lrelu(a1A.y + xrA.y) +
                   atA.z * lrelu(a1A.z + xrA.z) + atA.w * lrelu(a1A.w + xrA.w) +
                   atB.x * lrelu(a1B.x + xrB.x) + atB.y * lrelu(a1B.y + xrB.y) +
                   atB.z * lrelu(a1B.z + xrB.z) + atB.w * lrelu(a1B.w + xrB.w);
        t0 += __shfl_xor_sync(0xffffffffu, t0, 1);   // head reduce
        t1 += __shfl_xor_sync(0xffffffffu, t1, 1);
        float p0 = v0 ? __expf(t0) : 0.f;
        float p1 = v1 ? __expf(t1) : 0.f;
        den += p0 + p1;
        acc[0] += p0 * a0A.x + p1 * a1A.x;
        acc[1] += p0 * a0A.y + p1 * a1A.y;
        acc[2] += p0 * a0A.z + p1 * a1A.z;
        acc[3] += p0 * a0A.w + p1 * a1A.w;
        acc[4] += p0 * a0B.x + p1 * a1B.x;
        acc[5] += p0 * a0B.y + p1 * a1B.y;
        acc[6] += p0 * a0B.z + p1 * a1B.z;
        acc[7] += p0 * a0B.w + p1 * a1B.w;
    }
#pragma unroll
    for (int d = 8; d <= 16; d <<= 1) {
        den += __shfl_xor_sync(0xffffffffu, den, d);
#pragma unroll
        for (int j = 0; j < 8; j++) acc[j] += __shfl_xor_sync(0xffffffffu, acc[j], d);
    }
    if (g == 0) {
        float inv = 1.0f / (den + 1e-16f);
        const float4* b4 = (const float4*)(b1 + s * 8);
        float4 bA = b4[0], bB = b4[1];
        float4 vA, vB;
        vA.x = fmaxf(acc[0] * inv + bA.x, 0.f);
        vA.y = fmaxf(acc[1] * inv + bA.y, 0.f);
        vA.z = fmaxf(acc[2] * inv + bA.z, 0.f);
        vA.w = fmaxf(acc[3] * inv + bA.w, 0.f);
        vB.x = fmaxf(acc[4] * inv + bB.x, 0.f);
        vB.y = fmaxf(acc[5] * inv + bB.y, 0.f);
        vB.z = fmaxf(acc[6] * inv + bB.z, 0.f);
        vB.w = fmaxf(acc[7] * inv + bB.w, 0.f);
        float4* o4 = (float4*)(g_h1 + n * 64 + s * 8);
        o4[0] = vA; o4[1] = vB;
    }
}

// layer-2 agg: 1 head x 64 dims; 8-lane group reduce; fused mean-pool + count.
__global__ __launch_bounds__(256) void k_agg2(const float* __restrict__ att,
                                              const float* __restrict__ b2,
                                              const void* __restrict__ batch) {
    int warp = (blockIdx.x * 256 + threadIdx.x) >> 5;
    if (warp >= NN) return;
    int lane = threadIdx.x & 31;
    int g = lane >> 3, s = lane & 7;
    int n = warp;

    const float4* xr4 = (const float4*)(g_xr2 + n * 64 + s * 8);
    float4 xrA = xr4[0], xrB = xr4[1];
    float4 atA = ((const float4*)(att + s * 8))[0];
    float4 atB = ((const float4*)(att + s * 8))[1];

    float den = 0.f;
    float acc[8] = {0.f, 0.f, 0.f, 0.f, 0.f, 0.f, 0.f, 0.f};

    int k0 = g_off[n];
    int cnt = g_off[n + 1] - k0;
    const int* csrc = g_csrc + k0;
    int iters = (cnt + 7) >> 3;
    for (int it = 0; it < iters; it++) {
        int i0 = it * 8 + g * 2, i1 = i0 + 1;
        bool v0 = i0 < cnt, v1 = i1 < cnt;
        int s0 = v0 ? csrc[i0] : n;
        int s1 = v1 ? csrc[i1] : n;
        const float4* a40 = (const float4*)(g_xl2 + s0 * 64 + s * 8);
        const float4* a41 = (const float4*)(g_xl2 + s1 * 64 + s * 8);
        float4 a0A = a40[0], a0B = a40[1];
        float4 a1A = a41[0], a1B = a41[1];
        float t0 = atA.x * lrelu(a0A.x + xrA.x) + atA.y * lrelu(a0A.y + xrA.y) +
                   atA.z * lrelu(a0A.z + xrA.z) + atA.w * lrelu(a0A.w + xrA.w) +
                   atB.x * lrelu(a0B.x + xrB.x) + atB.y * lrelu(a0B.y + xrB.y) +
                   atB.z * lrelu(a0B.z + xrB.z) + atB.w * lrelu(a0B.w + xrB.w);
        float t1 = atA.x * lrelu(a1A.x + xrA.x) + atA.y * lrelu(a1A.y + xrA.y) +
                   atA.z * lrelu(a1A.z + xrA.z) + atA.w * lrelu(a1A.w + xrA.w) +
                   atB.x * lrelu(a1B.x + xrB.x) + atB.y * lrelu(a1B.y + xrB.y) +
                   atB.z * lrelu(a1B.z + xrB.z) + atB.w * lrelu(a1B.w + xrB.w);
        t0 += __shfl_xor_sync(0xffffffffu, t0, 1);
        t1 += __shfl_xor_sync(0xffffffffu, t1, 1);
        t0 += __shfl_xor_sync(0xffffffffu, t0, 2);
        t1 += __shfl_xor_sync(0xffffffffu, t1, 2);
        t0 += __shfl_xor_sync(0xffffffffu, t0, 4);
        t1 += __shfl_xor_sync(0xffffffffu, t1, 4);
        float p0 = v0 ? __expf(t0) : 0.f;
        float p1 = v1 ? __expf(t1) : 0.f;
        den += p0 + p1;
        acc[0] += p0 * a0A.x + p1 * a1A.x;
        acc[1] += p0 * a0A.y + p1 * a1A.y;
        acc[2] += p0 * a0A.z + p1 * a1A.z;
        acc[3] += p0 * a0A.w + p1 * a1A.w;
        acc[4] += p0 * a0B.x + p1 * a1B.x;
        acc[5] += p0 * a0B.y + p1 * a1B.y;
        acc[6] += p0 * a0B.z + p1 * a1B.z;
        acc[7] += p0 * a0B.w + p1 * a1B.w;
    }
#pragma unroll
    for (int d = 8; d <= 16; d <<= 1) {
        den += __shfl_xor_sync(0xffffffffu, den, d);
#pragma unroll
        for (int j = 0; j < 8; j++) acc[j] += __shfl_xor_sync(0xffffffffu, acc[j], d);
    }
    if (g == 0) {
        float inv = 1.0f / (den + 1e-16f);
        const float4* b4 = (const float4*)(b2 + s * 8);
        float4 bA = b4[0], bB = b4[1];
        float v0f = fmaxf(acc[0] * inv + bA.x, 0.f);
        float v1f = fmaxf(acc[1] * inv + bA.y, 0.f);
        float v2f = fmaxf(acc[2] * inv + bA.z, 0.f);
        float v3f = fmaxf(acc[3] * inv + bA.w, 0.f);
        float v4f = fmaxf(acc[4] * inv + bB.x, 0.f);
        float v5f = fmaxf(acc[5] * inv + bB.y, 0.f);
        float v6f = fmaxf(acc[6] * inv + bB.z, 0.f);
        float v7f = fmaxf(acc[7] * inv + bB.w, 0.f);
        int gid = ldidx(batch, n, g_b64);
        float* dst = g_pool + gid * 64 + s * 8;
        redAdd4(dst + 0, v0f, v1f, v2f, v3f);
        redAdd4(dst + 4, v4f, v5f, v6f, v7f);
        if (s == 0) atomicAdd(&g_cnt[gid], 1.0f);
    }
}

// predictor: out[g] = (pool[g]/max(cnt,1)) . Wp + bp
__global__ void k_pred(const float* __restrict__ Wp, const float* __restrict__ bp,
                       float* __restrict__ out) {
    int g = blockIdx.x * blockDim.x + threadIdx.x;
    if (g >= NG) return;
    float s = 0.f;
#pragma unroll
    for (int c = 0; c < 64; c++) s += g_pool[g * 64 + c] * Wp[c];
    out[g] = s / fmaxf(g_cnt[g], 1.0f) + bp[0];
}

// ---------------- launch --------------------------------------------------------
extern "C" void kernel_launch(void* const* d_in, const int* in_sizes, int n_in,
                              void* d_out, int out_size) {
    const float* x    = (const float*)d_in[0];
    const void*  ei   = d_in[1];
    const void*  batch= d_in[2];
    const float* W1l  = (const float*)d_in[3];
    const float* W1r  = (const float*)d_in[4];
    const float* att1 = (const float*)d_in[5];
    const float* b1   = (const float*)d_in[6];
    const float* W2l  = (const float*)d_in[7];
    const float* W2r  = (const float*)d_in[8];
    const float* att2 = (const float*)d_in[9];
    const float* b2   = (const float*)d_in[10];
    const float* Wp   = (const float*)d_in[11];
    const float* bp   = (const float*)d_in[12];
    float* out = (float*)d_out;

    const int T = 256;
    k_pre<<<GEMM1_BLOCKS + COUNT_BLOCKS, T>>>(x, W1l, W1r, ei, (const int*)batch);
    k_scanfill<<<SCAN_BLOCKS, T>>>(ei);
    k_agg1<<<(NN + 7) / 8, T>>>(att1, b1);
    k_gemm2<<<(NN + G2M - 1) / G2M, 512>>>(W2l, W2r);   // launch #4 -> profiled
    k_agg2<<<(NN + 7) / 8, T>>>(att2, b2, batch);
    k_pred<<<(NG + T - 1) / T, T>>>(Wp, bp, out);
}